// round 13
// baseline (speedup 1.0000x reference)
#include <cuda_runtime.h>
#include <cuda_bf16.h>
#include <cstdint>

#define NN 50000
#define DD 128
#define EE 800000

// ---------------------------------------------------------------------------
// Scratch (device globals — no allocation allowed)
// ---------------------------------------------------------------------------
__device__ __align__(256) float g_ya[NN * DD];     // A @ Wl
__device__ __align__(256) float g_yb[NN * DD];     // A @ (Wr+Ws)
__device__ __align__(256) float g_h0[NN * DD];
__device__ __align__(256) float g_h1[NN * DD];
__device__ __align__(256) float g_inv[NN];
__device__ __align__(256) int   g_cnt[NN];
__device__ __align__(256) int   g_rowptr[NN];
__device__ __align__(256) int   g_fill[NN];
__device__ __align__(256) int   g_src[EE];
__device__ __align__(256) int   g_dst[EE];
__device__ __align__(256) int   g_csrc[EE];
__device__ __align__(256) int   g_bsum2[256];      // block sums for scan
__device__ __align__(256) int   g_boff[256];       // block offsets for scan
// Fragment-ready bf16 hi/lo weight images per layer:
// L0 @0: hi 64KB + lo 64KB; L1 @131072: same; L2 @262144: hi 32KB + lo 32KB
__device__ __align__(1024) unsigned char g_wbf[327680];
__device__ __align__(256) float g_bsum[DD + DD + 64];
__device__ int g_is32;

// ---------------------------------------------------------------------------
// Edge dtype probe
// ---------------------------------------------------------------------------
__global__ void detect_kernel(const long long* __restrict__ ei) {
    if (blockIdx.x == 0 && threadIdx.x == 0) {
        int is32 = 0;
        for (int i = 0; i < 64; ++i) {
            long long v = ei[i];
            if (v < 0 || v >= NN) { is32 = 1; break; }
        }
        g_is32 = is32;
    }
}

// Convert edges to int32 arrays + histogram destinations (merged)
__global__ void convert_count_kernel(const void* __restrict__ ei) {
    int e = blockIdx.x * blockDim.x + threadIdx.x;
    if (e >= EE) return;
    int s, d;
    if (g_is32) {
        const int* p = (const int*)ei;
        s = p[e]; d = p[EE + e];
    } else {
        const long long* p = (const long long*)ei;
        s = (int)p[e]; d = (int)p[EE + e];
    }
    g_src[e] = s;
    g_dst[e] = d;
    atomicAdd(&g_cnt[d], 1);
}

// ---------------------------------------------------------------------------
// Weight prep (+ bias fold): FRAGMENT-READY bf16 hi/lo images of [Wl | Wr+Ws].
// B fragment layout for mma m16n8k16 (B is [n][k], n-major, K contiguous):
//   tile (nb = n/8, ks = k/16); lane = (n%8)*4 + ((k%16)%8)/2;
//   word = (k%16)/8; half = k%2;  addr = ((nb*8+ks)*32 + lane)*8 + word*4 + half*2
// nb is GLOBAL across W, so bytes [0, W*128) of each image = first output half.
// ---------------------------------------------------------------------------
__global__ void prepb_kernel(const float* __restrict__ Wl0, const float* __restrict__ Wr0, const float* __restrict__ Ws0,
                             const float* __restrict__ Wl1, const float* __restrict__ Wr1, const float* __restrict__ Ws1,
                             const float* __restrict__ Wl2, const float* __restrict__ Wr2, const float* __restrict__ Ws2,
                             const float* __restrict__ bl0, const float* __restrict__ bs0,
                             const float* __restrict__ bl1, const float* __restrict__ bs1,
                             const float* __restrict__ bl2, const float* __restrict__ bs2) {
    int t = blockIdx.x * blockDim.x + threadIdx.x;
    if (t >= 81920) {
        int b = t - 81920;
        if (b < DD)               g_bsum[b] = bl0[b] + bs0[b];
        else if (b < 2 * DD)      g_bsum[b] = bl1[b - DD] + bs1[b - DD];
        else if (b < 2 * DD + 64) g_bsum[b] = bl2[b - 2 * DD] + bs2[b - 2 * DD];
        return;
    }
    int dout, n, k; size_t base, hsize;
    const float *Wl, *Wr, *Ws;
    if (t < 32768)       { dout = 128; base = 0;      hsize = 65536; int u = t;         n = u >> 7; k = u & 127; Wl = Wl0; Wr = Wr0; Ws = Ws0; }
    else if (t < 65536)  { dout = 128; base = 131072; hsize = 65536; int u = t - 32768; n = u >> 7; k = u & 127; Wl = Wl1; Wr = Wr1; Ws = Ws1; }
    else                 { dout = 64;  base = 262144; hsize = 32768; int u = t - 65536; n = u >> 7; k = u & 127; Wl = Wl2; Wr = Wr2; Ws = Ws2; }
    float val = (n < dout) ? Wl[k * dout + n]
                           : (Wr[k * dout + (n - dout)] + Ws[k * dout + (n - dout)]);
    __nv_bfloat16 hi = __float2bfloat16(val);
    __nv_bfloat16 lo = __float2bfloat16(val - __bfloat162float(hi));
    int nb = n >> 3, ks = k >> 4, kin = k & 15;
    int lane = (n & 7) * 4 + ((kin & 7) >> 1);
    int word = kin >> 3, half = kin & 1;
    size_t off = (size_t)(((nb * 8 + ks) * 32 + lane) * 8 + word * 4 + half * 2);
    *(__nv_bfloat16*)(g_wbf + base + off)         = hi;
    *(__nv_bfloat16*)(g_wbf + base + hsize + off) = lo;
}

// ---------------------------------------------------------------------------
// CSR build: zero, count (merged above), 3-stage scan, fill
// ---------------------------------------------------------------------------
__global__ void zero_cnt_kernel() {
    int t = blockIdx.x * blockDim.x + threadIdx.x;
    if (t < NN) g_cnt[t] = 0;
}
__global__ void scanA_kernel() {
    __shared__ int sh[256];
    int t = threadIdx.x;
    int idx = blockIdx.x * 256 + t;
    sh[t] = (idx < NN) ? g_cnt[idx] : 0;
    __syncthreads();
    for (int off = 128; off > 0; off >>= 1) {
        if (t < off) sh[t] += sh[t + off];
        __syncthreads();
    }
    if (t == 0) g_bsum2[blockIdx.x] = sh[0];
}
__global__ void scanB_kernel(int nblocks) {
    __shared__ int sh[256];
    int t = threadIdx.x;
    sh[t] = (t < nblocks) ? g_bsum2[t] : 0;
    __syncthreads();
    for (int off = 1; off < 256; off <<= 1) {
        int v = (t >= off) ? sh[t - off] : 0;
        __syncthreads();
        sh[t] += v;
        __syncthreads();
    }
    if (t < nblocks) g_boff[t] = (t == 0) ? 0 : sh[t - 1];
}
__global__ void scanC_kernel() {
    __shared__ int sh[256];
    int t = threadIdx.x;
    int idx = blockIdx.x * 256 + t;
    int c = (idx < NN) ? g_cnt[idx] : 0;
    sh[t] = c;
    __syncthreads();
    for (int off = 1; off < 256; off <<= 1) {
        int v = (t >= off) ? sh[t - off] : 0;
        __syncthreads();
        sh[t] += v;
        __syncthreads();
    }
    if (idx < NN) {
        int run = g_boff[blockIdx.x] + sh[t] - c;   // exclusive
        g_rowptr[idx] = run;
        g_fill[idx]   = run;
        g_inv[idx]    = 1.0f / fmaxf((float)c, 1.0f);
    }
}
__global__ void fill_kernel() {
    int e = blockIdx.x * blockDim.x + threadIdx.x;
    if (e >= EE) return;
    int pos = atomicAdd(&g_fill[g_dst[e]], 1);
    g_csrc[pos] = g_src[e];
}

// ---------------------------------------------------------------------------
// mma.sync m16n8k16 bf16 (baseline PTX) + cp.async helpers (sm_80 baseline)
// ---------------------------------------------------------------------------
__device__ __forceinline__ void mma_16816(float* c, const uint32_t* a, const uint32_t* b) {
    asm volatile("mma.sync.aligned.m16n8k16.row.col.f32.bf16.bf16.f32 "
                 "{%0,%1,%2,%3}, {%4,%5,%6,%7}, {%8,%9}, {%0,%1,%2,%3};"
                 : "+f"(c[0]), "+f"(c[1]), "+f"(c[2]), "+f"(c[3])
                 : "r"(a[0]), "r"(a[1]), "r"(a[2]), "r"(a[3]), "r"(b[0]), "r"(b[1]));
}
__device__ __forceinline__ uint32_t smem_u32(const void* p) {
    uint32_t a;
    asm("{ .reg .u64 t; cvta.to.shared.u64 t, %1; cvt.u32.u64 %0, t; }" : "=r"(a) : "l"(p));
    return a;
}
__device__ __forceinline__ void cp_async16(uint32_t saddr, const void* gaddr) {
    asm volatile("cp.async.cg.shared.global [%0], [%1], 16;" :: "r"(saddr), "l"(gaddr));
}

// ---------------------------------------------------------------------------
// Tensor-core GEMM via split-bf16 3-MMA, 2 CTAs/SM phase overlap.
// Tile: M=64 rows x NTILE (=W/2=DOUT) output cols; blockIdx.y selects half:
//   y=0 -> C = g_ya (Wl half), y=1 -> C = g_yb (Wr+Ws half)
// 256 threads, 8 warps as WM(m) x WN(n); WN = NTILE/32.
// SMEM: A_hi 16KB | A_lo 16KB | B_hi HALFB | B_lo HALFB  (HALFB = W*128)
// ---------------------------------------------------------------------------
template<int W, int DOUT, int SRC>
__global__ void __launch_bounds__(256, 2)
tc_gemm_kernel(const float* __restrict__ Ax_ext, int layerOff) {
    constexpr int HALFB = W * 128;           // bytes per half of one image
    constexpr int NTILE = W / 2;             // output columns per CTA (== DOUT)
    constexpr int WN = NTILE / 32;           // warps in n: 4 (W=256), 2 (W=128)
    constexpr int WM = 8 / WN;               // warps in m: 2, 4
    constexpr int MT = 64 / (WM * 16);       // m-subtiles per warp: 2, 1
    constexpr int A_LO = 16384;
    constexpr int B_HI = 32768;
    constexpr int B_LO = 32768 + HALFB;

    extern __shared__ char smem[];
    int tid = threadIdx.x, wid = tid >> 5, lane = tid & 31;
    int wm = wid / WN, wn = wid % WN;
    int row0 = blockIdx.x * 64;
    int yh = blockIdx.y;
    const float* A = (SRC == 0) ? Ax_ext : (SRC == 1) ? g_h0 : g_h1;
    uint32_t sbase = smem_u32(smem);

    // --- B half images via cp.async (overlaps with A convert below)
    {
        const char* srcH = (const char*)g_wbf + layerOff + yh * HALFB;
        const char* srcL = (const char*)g_wbf + layerOff + W * 256 + yh * HALFB;
        constexpr int NCH = HALFB / 16;      // 16B chunks per half image
        #pragma unroll
        for (int i = 0; i < NCH / 256; ++i) {
            int c = tid + i * 256;
            cp_async16(sbase + B_HI + c * 16, srcH + c * 16);
            cp_async16(sbase + B_LO + c * 16, srcL + c * 16);
        }
        asm volatile("cp.async.commit_group;");
    }

    // --- load A (64 x 128 f32), split to bf16 hi/lo, store fragment-ready
    #pragma unroll
    for (int i = 0; i < 8; ++i) {
        int f = tid + i * 256;               // 0..2047
        int r = f >> 5;                      // row 0..63
        int k = (f & 31) * 4;
        int grow = row0 + r;
        float4 v = make_float4(0.f, 0.f, 0.f, 0.f);
        if (grow < NN) v = *(const float4*)(A + (size_t)grow * DD + k);
        uint32_t h0, h1, l0, l1;
        {
            __nv_bfloat162 a, b, c, d;
            a.x = __float2bfloat16(v.x); a.y = __float2bfloat16(v.y);
            b.x = __float2bfloat16(v.z); b.y = __float2bfloat16(v.w);
            c.x = __float2bfloat16(v.x - __bfloat162float(a.x));
            c.y = __float2bfloat16(v.y - __bfloat162float(a.y));
            d.x = __float2bfloat16(v.z - __bfloat162float(b.x));
            d.y = __float2bfloat16(v.w - __bfloat162float(b.y));
            h0 = *(uint32_t*)&a; h1 = *(uint32_t*)&b;
            l0 = *(uint32_t*)&c; l1 = *(uint32_t*)&d;
        }
        int rb = r >> 4, g = r & 15;
        int ks = k >> 4, kin = k & 15;
        int w = (g >> 3) + ((kin >> 3) << 1);
        int ln0 = (g & 7) * 4 + ((kin & 7) >> 1);
        uint32_t tb = (uint32_t)(((rb * 8 + ks) * 32) * 16 + w * 4);
        *(uint32_t*)(smem + tb + ln0 * 16)              = h0;
        *(uint32_t*)(smem + tb + (ln0 + 1) * 16)        = h1;
        *(uint32_t*)(smem + A_LO + tb + ln0 * 16)       = l0;
        *(uint32_t*)(smem + A_LO + tb + (ln0 + 1) * 16) = l1;
    }

    asm volatile("cp.async.wait_group 0;" ::: "memory");
    __syncthreads();

    float acc[MT][4][4];
    #pragma unroll
    for (int mt = 0; mt < MT; ++mt)
        #pragma unroll
        for (int nt = 0; nt < 4; ++nt)
            #pragma unroll
            for (int j = 0; j < 4; ++j) acc[mt][nt][j] = 0.f;

    #pragma unroll 2
    for (int ks = 0; ks < 8; ++ks) {
        uint4 ah[MT], al[MT];
        #pragma unroll
        for (int mt = 0; mt < MT; ++mt) {
            int rb = wm * MT + mt;
            uint32_t ao = (uint32_t)(((rb * 8 + ks) * 32 + lane) * 16);
            ah[mt] = *(const uint4*)(smem + ao);
            al[mt] = *(const uint4*)(smem + A_LO + ao);
        }
        #pragma unroll
        for (int nt = 0; nt < 4; ++nt) {
            int nb = wn * 4 + nt;            // [0, NTILE/8)
            uint32_t bo = (uint32_t)(((nb * 8 + ks) * 32 + lane) * 8);
            uint2 bh = *(const uint2*)(smem + B_HI + bo);
            uint2 bl = *(const uint2*)(smem + B_LO + bo);
            #pragma unroll
            for (int mt = 0; mt < MT; ++mt) {
                mma_16816(acc[mt][nt], (const uint32_t*)&ah[mt], (const uint32_t*)&bh);
                mma_16816(acc[mt][nt], (const uint32_t*)&ah[mt], (const uint32_t*)&bl);
                mma_16816(acc[mt][nt], (const uint32_t*)&al[mt], (const uint32_t*)&bh);
            }
        }
    }

    // --- store: destination matrix uniform per CTA
    {
        float* dst = yh ? g_yb : g_ya;
        int gid = lane >> 2, tig = lane & 3;
        #pragma unroll
        for (int mt = 0; mt < MT; ++mt) {
            int r0 = row0 + (wm * MT + mt) * 16 + gid;
            #pragma unroll
            for (int nt = 0; nt < 4; ++nt) {
                int col = wn * 32 + nt * 8 + 2 * tig;   // [0, DOUT)
                if (r0 < NN) {
                    float2 v0 = make_float2(acc[mt][nt][0], acc[mt][nt][1]);
                    *(float2*)(dst + (size_t)r0 * DOUT + col) = v0;
                }
                if (r0 + 8 < NN) {
                    float2 v1 = make_float2(acc[mt][nt][2], acc[mt][nt][3]);
                    *(float2*)(dst + (size_t)(r0 + 8) * DOUT + col) = v1;
                }
            }
        }
    }
}

// ---------------------------------------------------------------------------
// Aggregation: one warp per node, edges unrolled x4 (independent accumulators).
// ---------------------------------------------------------------------------
template<int DO, int DST, int RELU>
__global__ void agg_kernel(float* __restrict__ out_ext, int boff) {
    int gt = blockIdx.x * blockDim.x + threadIdx.x;
    int node = gt >> 5;
    int lane = gt & 31;
    if (node >= NN) return;
    float* out = (DST == 0) ? out_ext : (DST == 1) ? g_h0 : g_h1;
    const float* bias = g_bsum + boff;

    int start = g_rowptr[node];
    int deg   = g_cnt[node];
    float inv = g_inv[node];

    if (DO == 128) {
        float4 a0 = make_float4(0.f, 0.f, 0.f, 0.f), a1 = a0, a2 = a0, a3 = a0;
        int i = 0;
        for (; i + 3 < deg; i += 4) {
            int s0 = g_csrc[start + i],     s1 = g_csrc[start + i + 1];
            int s2 = g_csrc[start + i + 2], s3 = g_csrc[start + i + 3];
            float4 v0 = *(const float4*)(g_ya + (size_t)s0 * 128 + lane * 4);
            float4 v1 = *(const float4*)(g_ya + (size_t)s1 * 128 + lane * 4);
            float4 v2 = *(const float4*)(g_ya + (size_t)s2 * 128 + lane * 4);
            float4 v3 = *(const float4*)(g_ya + (size_t)s3 * 128 + lane * 4);
            a0.x += v0.x; a0.y += v0.y; a0.z += v0.z; a0.w += v0.w;
            a1.x += v1.x; a1.y += v1.y; a1.z += v1.z; a1.w += v1.w;
            a2.x += v2.x; a2.y += v2.y; a2.z += v2.z; a2.w += v2.w;
            a3.x += v3.x; a3.y += v3.y; a3.z += v3.z; a3.w += v3.w;
        }
        for (; i < deg; ++i) {
            int s0 = g_csrc[start + i];
            float4 v0 = *(const float4*)(g_ya + (size_t)s0 * 128 + lane * 4);
            a0.x += v0.x; a0.y += v0.y; a0.z += v0.z; a0.w += v0.w;
        }
        a0.x += a1.x + a2.x + a3.x; a0.y += a1.y + a2.y + a3.y;
        a0.z += a1.z + a2.z + a3.z; a0.w += a1.w + a2.w + a3.w;
        float4 yb = *(const float4*)(g_yb + (size_t)node * 128 + lane * 4);
        float4 r;
        r.x = a0.x * inv + yb.x + bias[lane * 4 + 0];
        r.y = a0.y * inv + yb.y + bias[lane * 4 + 1];
        r.z = a0.z * inv + yb.z + bias[lane * 4 + 2];
        r.w = a0.w * inv + yb.w + bias[lane * 4 + 3];
        if (RELU) {
            r.x = fmaxf(r.x, 0.f); r.y = fmaxf(r.y, 0.f);
            r.z = fmaxf(r.z, 0.f); r.w = fmaxf(r.w, 0.f);
        }
        *(float4*)(out + (size_t)node * 128 + lane * 4) = r;
    } else {
        float2 a0 = make_float2(0.f, 0.f), a1 = a0, a2 = a0, a3 = a0;
        int i = 0;
        for (; i + 3 < deg; i += 4) {
            int s0 = g_csrc[start + i],     s1 = g_csrc[start + i + 1];
            int s2 = g_csrc[start + i + 2], s3 = g_csrc[start + i + 3];
            float2 v0 = *(const float2*)(g_ya + (size_t)s0 * 64 + lane * 2);
            float2 v1 = *(const float2*)(g_ya + (size_t)s1 * 64 + lane * 2);
            float2 v2 = *(const float2*)(g_ya + (size_t)s2 * 64 + lane * 2);
            float2 v3 = *(const float2*)(g_ya + (size_t)s3 * 64 + lane * 2);
            a0.x += v0.x; a0.y += v0.y;  a1.x += v1.x; a1.y += v1.y;
            a2.x += v2.x; a2.y += v2.y;  a3.x += v3.x; a3.y += v3.y;
        }
        for (; i < deg; ++i) {
            int s0 = g_csrc[start + i];
            float2 v0 = *(const float2*)(g_ya + (size_t)s0 * 64 + lane * 2);
            a0.x += v0.x; a0.y += v0.y;
        }
        a0.x += a1.x + a2.x + a3.x; a0.y += a1.y + a2.y + a3.y;
        float2 yb = *(const float2*)(g_yb + (size_t)node * 64 + lane * 2);
        float2 r;
        r.x = a0.x * inv + yb.x + bias[lane * 2 + 0];
        r.y = a0.y * inv + yb.y + bias[lane * 2 + 1];
        if (RELU) { r.x = fmaxf(r.x, 0.f); r.y = fmaxf(r.y, 0.f); }
        *(float2*)(out + (size_t)node * 64 + lane * 2) = r;
    }
}

// ---------------------------------------------------------------------------
extern "C" void kernel_launch(void* const* d_in, const int* in_sizes, int n_in,
                              void* d_out, int out_size) {
    const float* x  = (const float*)d_in[0];
    const void*  ei = d_in[1];
    const float* Wl0 = (const float*)d_in[4];
    const float* bl0 = (const float*)d_in[5];
    const float* Wr0 = (const float*)d_in[6];
    const float* Ws0 = (const float*)d_in[7];
    const float* bs0 = (const float*)d_in[8];
    const float* Wl1 = (const float*)d_in[9];
    const float* bl1 = (const float*)d_in[10];
    const float* Wr1 = (const float*)d_in[11];
    const float* Ws1 = (const float*)d_in[12];
    const float* bs1 = (const float*)d_in[13];
    const float* Wl2 = (const float*)d_in[14];
    const float* bl2 = (const float*)d_in[15];
    const float* Wr2 = (const float*)d_in[16];
    const float* Ws2 = (const float*)d_in[17];
    const float* bs2 = (const float*)d_in[18];
    float* out = (float*)d_out;

    const int S256 = 32768 + 2 * 256 * 128;   // 98304  (W=256)
    const int S128 = 32768 + 2 * 128 * 128;   // 65536  (W=128)
    cudaFuncSetAttribute(tc_gemm_kernel<256, 128, 0>, cudaFuncAttributeMaxDynamicSharedMemorySize, S256);
    cudaFuncSetAttribute(tc_gemm_kernel<256, 128, 1>, cudaFuncAttributeMaxDynamicSharedMemorySize, S256);
    cudaFuncSetAttribute(tc_gemm_kernel<128, 64, 2>,  cudaFuncAttributeMaxDynamicSharedMemorySize, S128);

    const int eBlocks    = (EE + 255) / 256;
    const dim3 gemmGrid((NN + 63) / 64, 2);      // (782, 2)
    const int aggBlocks  = (NN * 32) / 256;      // 6250
    const int scanBlocks = (NN + 255) / 256;     // 196

    // Order: tc_gemm L0 stays at launch #3 (0-based) for ncu
    prepb_kernel<<<322, 256>>>(Wl0, Wr0, Ws0, Wl1, Wr1, Ws1, Wl2, Wr2, Ws2,
                               bl0, bs0, bl1, bs1, bl2, bs2);               // 0
    zero_cnt_kernel<<<scanBlocks, 256>>>();                                  // 1
    detect_kernel<<<1, 32>>>((const long long*)ei);                          // 2

    tc_gemm_kernel<256, 128, 0><<<gemmGrid, 256, S256>>>(x, 0);              // 3 (profiled)

    convert_count_kernel<<<eBlocks, 256>>>(ei);                              // 4
    scanA_kernel<<<scanBlocks, 256>>>();                                     // 5
    scanB_kernel<<<1, 256>>>(scanBlocks);                                    // 6
    scanC_kernel<<<scanBlocks, 256>>>();                                     // 7
    fill_kernel<<<eBlocks, 256>>>();                                         // 8

    agg_kernel<128, 1, 1><<<aggBlocks, 256>>>(nullptr, 0);                   // 9

    tc_gemm_kernel<256, 128, 1><<<gemmGrid, 256, S256>>>(nullptr, 131072);   // 10
    agg_kernel<128, 2, 1><<<aggBlocks, 256>>>(nullptr, DD);                  // 11

    tc_gemm_kernel<128, 64, 2><<<gemmGrid, 256, S128>>>(nullptr, 262144);    // 12
    agg_kernel<64, 0, 0><<<aggBlocks, 256>>>(out, 2 * DD);                   // 13
}

// round 14
// speedup vs baseline: 1.0139x; 1.0139x over previous
#include <cuda_runtime.h>
#include <cuda_bf16.h>
#include <cstdint>

#define NN 50000
#define DD 128
#define EE 800000

// ---------------------------------------------------------------------------
// Scratch (device globals — no allocation allowed)
// ---------------------------------------------------------------------------
__device__ __align__(256) float g_ya[NN * DD];     // A @ Wl
__device__ __align__(256) float g_yb[NN * DD];     // A @ (Wr+Ws)
__device__ __align__(256) float g_h0[NN * DD];
__device__ __align__(256) float g_h1[NN * DD];
__device__ __align__(256) float g_inv[NN];
__device__ __align__(256) int   g_cnt[NN];
__device__ __align__(256) int   g_rowptr[NN];
__device__ __align__(256) int   g_fill[NN];
__device__ __align__(256) int   g_src[EE];
__device__ __align__(256) int   g_dst[EE];
__device__ __align__(256) int   g_csrc[EE];
__device__ __align__(256) int   g_bsum2[256];      // block sums for scan
__device__ __align__(256) int   g_boff[256];       // block offsets for scan
// Fragment-ready bf16 hi/lo weight images per layer:
// L0 @0: hi 64KB + lo 64KB; L1 @131072: same; L2 @262144: hi 32KB + lo 32KB
__device__ __align__(1024) unsigned char g_wbf[327680];
__device__ __align__(256) float g_bsum[DD + DD + 64];
__device__ int g_is32;

// ---------------------------------------------------------------------------
// Edge dtype probe
// ---------------------------------------------------------------------------
__global__ void detect_kernel(const long long* __restrict__ ei) {
    if (blockIdx.x == 0 && threadIdx.x == 0) {
        int is32 = 0;
        for (int i = 0; i < 64; ++i) {
            long long v = ei[i];
            if (v < 0 || v >= NN) { is32 = 1; break; }
        }
        g_is32 = is32;
    }
}

// Convert edges to int32 arrays + histogram destinations (merged)
__global__ void convert_count_kernel(const void* __restrict__ ei) {
    int e = blockIdx.x * blockDim.x + threadIdx.x;
    if (e >= EE) return;
    int s, d;
    if (g_is32) {
        const int* p = (const int*)ei;
        s = p[e]; d = p[EE + e];
    } else {
        const long long* p = (const long long*)ei;
        s = (int)p[e]; d = (int)p[EE + e];
    }
    g_src[e] = s;
    g_dst[e] = d;
    atomicAdd(&g_cnt[d], 1);
}

// ---------------------------------------------------------------------------
// Weight prep (+ bias fold): FRAGMENT-READY bf16 hi/lo images of [Wl | Wr+Ws].
// B fragment layout for mma m16n8k16 (B is [n][k], n-major, K contiguous):
//   tile (nb = n/8, ks = k/16); lane = (n%8)*4 + ((k%16)%8)/2;
//   word = (k%16)/8; half = k%2;  addr = ((nb*8+ks)*32 + lane)*8 + word*4 + half*2
// nb is GLOBAL across W (concatenated [Wl | Wr+Ws] width).
// ---------------------------------------------------------------------------
__global__ void prepb_kernel(const float* __restrict__ Wl0, const float* __restrict__ Wr0, const float* __restrict__ Ws0,
                             const float* __restrict__ Wl1, const float* __restrict__ Wr1, const float* __restrict__ Ws1,
                             const float* __restrict__ Wl2, const float* __restrict__ Wr2, const float* __restrict__ Ws2,
                             const float* __restrict__ bl0, const float* __restrict__ bs0,
                             const float* __restrict__ bl1, const float* __restrict__ bs1,
                             const float* __restrict__ bl2, const float* __restrict__ bs2) {
    int t = blockIdx.x * blockDim.x + threadIdx.x;
    if (t >= 81920) {
        int b = t - 81920;
        if (b < DD)               g_bsum[b] = bl0[b] + bs0[b];
        else if (b < 2 * DD)      g_bsum[b] = bl1[b - DD] + bs1[b - DD];
        else if (b < 2 * DD + 64) g_bsum[b] = bl2[b - 2 * DD] + bs2[b - 2 * DD];
        return;
    }
    int dout, n, k; size_t base, hsize;
    const float *Wl, *Wr, *Ws;
    if (t < 32768)       { dout = 128; base = 0;      hsize = 65536; int u = t;         n = u >> 7; k = u & 127; Wl = Wl0; Wr = Wr0; Ws = Ws0; }
    else if (t < 65536)  { dout = 128; base = 131072; hsize = 65536; int u = t - 32768; n = u >> 7; k = u & 127; Wl = Wl1; Wr = Wr1; Ws = Ws1; }
    else                 { dout = 64;  base = 262144; hsize = 32768; int u = t - 65536; n = u >> 7; k = u & 127; Wl = Wl2; Wr = Wr2; Ws = Ws2; }
    float val = (n < dout) ? Wl[k * dout + n]
                           : (Wr[k * dout + (n - dout)] + Ws[k * dout + (n - dout)]);
    __nv_bfloat16 hi = __float2bfloat16(val);
    __nv_bfloat16 lo = __float2bfloat16(val - __bfloat162float(hi));
    int nb = n >> 3, ks = k >> 4, kin = k & 15;
    int lane = (n & 7) * 4 + ((kin & 7) >> 1);
    int word = kin >> 3, half = kin & 1;
    size_t off = (size_t)(((nb * 8 + ks) * 32 + lane) * 8 + word * 4 + half * 2);
    *(__nv_bfloat16*)(g_wbf + base + off)         = hi;
    *(__nv_bfloat16*)(g_wbf + base + hsize + off) = lo;
}

// ---------------------------------------------------------------------------
// CSR build: zero, count (merged above), 3-stage scan, fill
// ---------------------------------------------------------------------------
__global__ void zero_cnt_kernel() {
    int t = blockIdx.x * blockDim.x + threadIdx.x;
    if (t < NN) g_cnt[t] = 0;
}
__global__ void scanA_kernel() {
    __shared__ int sh[256];
    int t = threadIdx.x;
    int idx = blockIdx.x * 256 + t;
    sh[t] = (idx < NN) ? g_cnt[idx] : 0;
    __syncthreads();
    for (int off = 128; off > 0; off >>= 1) {
        if (t < off) sh[t] += sh[t + off];
        __syncthreads();
    }
    if (t == 0) g_bsum2[blockIdx.x] = sh[0];
}
__global__ void scanB_kernel(int nblocks) {
    __shared__ int sh[256];
    int t = threadIdx.x;
    sh[t] = (t < nblocks) ? g_bsum2[t] : 0;
    __syncthreads();
    for (int off = 1; off < 256; off <<= 1) {
        int v = (t >= off) ? sh[t - off] : 0;
        __syncthreads();
        sh[t] += v;
        __syncthreads();
    }
    if (t < nblocks) g_boff[t] = (t == 0) ? 0 : sh[t - 1];
}
__global__ void scanC_kernel() {
    __shared__ int sh[256];
    int t = threadIdx.x;
    int idx = blockIdx.x * 256 + t;
    int c = (idx < NN) ? g_cnt[idx] : 0;
    sh[t] = c;
    __syncthreads();
    for (int off = 1; off < 256; off <<= 1) {
        int v = (t >= off) ? sh[t - off] : 0;
        __syncthreads();
        sh[t] += v;
        __syncthreads();
    }
    if (idx < NN) {
        int run = g_boff[blockIdx.x] + sh[t] - c;   // exclusive
        g_rowptr[idx] = run;
        g_fill[idx]   = run;
        g_inv[idx]    = 1.0f / fmaxf((float)c, 1.0f);
    }
}
__global__ void fill_kernel() {
    int e = blockIdx.x * blockDim.x + threadIdx.x;
    if (e >= EE) return;
    int pos = atomicAdd(&g_fill[g_dst[e]], 1);
    g_csrc[pos] = g_src[e];
}

// ---------------------------------------------------------------------------
// mma.sync m16n8k16 bf16 (baseline PTX) + cp.async helpers (sm_80 baseline)
// ---------------------------------------------------------------------------
__device__ __forceinline__ void mma_16816(float* c, const uint32_t* a, const uint32_t* b) {
    asm volatile("mma.sync.aligned.m16n8k16.row.col.f32.bf16.bf16.f32 "
                 "{%0,%1,%2,%3}, {%4,%5,%6,%7}, {%8,%9}, {%0,%1,%2,%3};"
                 : "+f"(c[0]), "+f"(c[1]), "+f"(c[2]), "+f"(c[3])
                 : "r"(a[0]), "r"(a[1]), "r"(a[2]), "r"(a[3]), "r"(b[0]), "r"(b[1]));
}
__device__ __forceinline__ uint32_t smem_u32(const void* p) {
    uint32_t a;
    asm("{ .reg .u64 t; cvta.to.shared.u64 t, %1; cvt.u32.u64 %0, t; }" : "=r"(a) : "l"(p));
    return a;
}
__device__ __forceinline__ void cp_async16(uint32_t saddr, const void* gaddr) {
    asm volatile("cp.async.cg.shared.global [%0], [%1], 16;" :: "r"(saddr), "l"(gaddr));
}

// ---------------------------------------------------------------------------
// Tensor-core GEMM via split-bf16 3-MMA, fat tiles to cut smem traffic.
// CTA tile: 128 rows x ALL W concatenated output cols (one A pass feeds both
// g_ya and g_yb). 256 threads, 8 warps as 2m x 4n -> warp tile 64 x (W/4).
// SMEM: A_hi 32KB | A_lo 32KB | B_hi W*256 | B_lo W*256
//   W=256: 192KB, 1 CTA/SM.  W=128: 128KB.
// ---------------------------------------------------------------------------
template<int W, int DOUT, int SRC>
__global__ void __launch_bounds__(256, 1)
tc_gemm_kernel(const float* __restrict__ Ax_ext, int layerOff) {
    constexpr int BIMG = W * 256;            // bytes per B image (hi or lo)
    constexpr int TN = W / 4;                // warp n-extent: 64 (W=256), 32 (W=128)
    constexpr int NT = TN / 8;               // n-subtiles: 8, 4
    constexpr int A_LO = 32768;
    constexpr int B_HI = 65536;
    constexpr int B_LO = 65536 + BIMG;

    extern __shared__ char smem[];
    int tid = threadIdx.x, wid = tid >> 5, lane = tid & 31;
    int wm = wid >> 2, wn = wid & 3;         // 2m x 4n
    int row0 = blockIdx.x * 128;
    const float* A = (SRC == 0) ? Ax_ext : (SRC == 1) ? g_h0 : g_h1;
    uint32_t sbase = smem_u32(smem);

    // --- B full images via cp.async (overlaps with A convert below)
    {
        const char* srcH = (const char*)g_wbf + layerOff;
        const char* srcL = srcH + BIMG;
        constexpr int NCH = BIMG / 16;       // 16B chunks per image
        #pragma unroll
        for (int i = 0; i < NCH / 256; ++i) {
            int c = tid + i * 256;
            cp_async16(sbase + B_HI + c * 16, srcH + c * 16);
            cp_async16(sbase + B_LO + c * 16, srcL + c * 16);
        }
        asm volatile("cp.async.commit_group;");
    }

    // --- load A (128 x 128 f32), split to bf16 hi/lo, store fragment-ready
    #pragma unroll
    for (int i = 0; i < 16; ++i) {
        int f = tid + i * 256;               // 0..4095
        int r = f >> 5;                      // row 0..127
        int k = (f & 31) * 4;
        int grow = row0 + r;
        float4 v = make_float4(0.f, 0.f, 0.f, 0.f);
        if (grow < NN) v = *(const float4*)(A + (size_t)grow * DD + k);
        uint32_t h0, h1, l0, l1;
        {
            __nv_bfloat162 a, b, c, d;
            a.x = __float2bfloat16(v.x); a.y = __float2bfloat16(v.y);
            b.x = __float2bfloat16(v.z); b.y = __float2bfloat16(v.w);
            c.x = __float2bfloat16(v.x - __bfloat162float(a.x));
            c.y = __float2bfloat16(v.y - __bfloat162float(a.y));
            d.x = __float2bfloat16(v.z - __bfloat162float(b.x));
            d.y = __float2bfloat16(v.w - __bfloat162float(b.y));
            h0 = *(uint32_t*)&a; h1 = *(uint32_t*)&b;
            l0 = *(uint32_t*)&c; l1 = *(uint32_t*)&d;
        }
        int rb = r >> 4, g = r & 15;         // rb 0..7
        int ks = k >> 4, kin = k & 15;
        int w = (g >> 3) + ((kin >> 3) << 1);
        int ln0 = (g & 7) * 4 + ((kin & 7) >> 1);
        uint32_t tb = (uint32_t)(((rb * 8 + ks) * 32) * 16 + w * 4);
        *(uint32_t*)(smem + tb + ln0 * 16)              = h0;
        *(uint32_t*)(smem + tb + (ln0 + 1) * 16)        = h1;
        *(uint32_t*)(smem + A_LO + tb + ln0 * 16)       = l0;
        *(uint32_t*)(smem + A_LO + tb + (ln0 + 1) * 16) = l1;
    }

    asm volatile("cp.async.wait_group 0;" ::: "memory");
    __syncthreads();

    float acc[4][NT][4];
    #pragma unroll
    for (int mt = 0; mt < 4; ++mt)
        #pragma unroll
        for (int nt = 0; nt < NT; ++nt)
            #pragma unroll
            for (int j = 0; j < 4; ++j) acc[mt][nt][j] = 0.f;

    #pragma unroll 1
    for (int ks = 0; ks < 8; ++ks) {
        uint4 ah[4], al[4];
        #pragma unroll
        for (int mt = 0; mt < 4; ++mt) {
            int rb = wm * 4 + mt;            // 0..7
            uint32_t ao = (uint32_t)(((rb * 8 + ks) * 32 + lane) * 16);
            ah[mt] = *(const uint4*)(smem + ao);
            al[mt] = *(const uint4*)(smem + A_LO + ao);
        }
        #pragma unroll
        for (int nt = 0; nt < NT; ++nt) {
            int nb = wn * NT + nt;           // global nb over W
            uint32_t bo = (uint32_t)(((nb * 8 + ks) * 32 + lane) * 8);
            uint2 bh = *(const uint2*)(smem + B_HI + bo);
            uint2 bl = *(const uint2*)(smem + B_LO + bo);
            #pragma unroll
            for (int mt = 0; mt < 4; ++mt) {
                mma_16816(acc[mt][nt], (const uint32_t*)&ah[mt], (const uint32_t*)&bh);
                mma_16816(acc[mt][nt], (const uint32_t*)&ah[mt], (const uint32_t*)&bl);
                mma_16816(acc[mt][nt], (const uint32_t*)&al[mt], (const uint32_t*)&bh);
            }
        }
    }

    // --- store: warp n-strip is entirely inside one destination matrix
    {
        float* dst = (wn < 2) ? g_ya : g_yb;
        int colbase = wn * TN - ((wn < 2) ? 0 : DOUT);
        int gid = lane >> 2, tig = lane & 3;
        #pragma unroll
        for (int mt = 0; mt < 4; ++mt) {
            int r0 = row0 + wm * 64 + mt * 16 + gid;
            #pragma unroll
            for (int nt = 0; nt < NT; ++nt) {
                int col = colbase + nt * 8 + 2 * tig;
                if (r0 < NN) {
                    float2 v0 = make_float2(acc[mt][nt][0], acc[mt][nt][1]);
                    *(float2*)(dst + (size_t)r0 * DOUT + col) = v0;
                }
                if (r0 + 8 < NN) {
                    float2 v1 = make_float2(acc[mt][nt][2], acc[mt][nt][3]);
                    *(float2*)(dst + (size_t)(r0 + 8) * DOUT + col) = v1;
                }
            }
        }
    }
}

// ---------------------------------------------------------------------------
// Aggregation: one warp per node, edges unrolled x4 (independent accumulators).
// ---------------------------------------------------------------------------
template<int DO, int DST, int RELU>
__global__ void agg_kernel(float* __restrict__ out_ext, int boff) {
    int gt = blockIdx.x * blockDim.x + threadIdx.x;
    int node = gt >> 5;
    int lane = gt & 31;
    if (node >= NN) return;
    float* out = (DST == 0) ? out_ext : (DST == 1) ? g_h0 : g_h1;
    const float* bias = g_bsum + boff;

    int start = g_rowptr[node];
    int deg   = g_cnt[node];
    float inv = g_inv[node];

    if (DO == 128) {
        float4 a0 = make_float4(0.f, 0.f, 0.f, 0.f), a1 = a0, a2 = a0, a3 = a0;
        int i = 0;
        for (; i + 3 < deg; i += 4) {
            int s0 = g_csrc[start + i],     s1 = g_csrc[start + i + 1];
            int s2 = g_csrc[start + i + 2], s3 = g_csrc[start + i + 3];
            float4 v0 = *(const float4*)(g_ya + (size_t)s0 * 128 + lane * 4);
            float4 v1 = *(const float4*)(g_ya + (size_t)s1 * 128 + lane * 4);
            float4 v2 = *(const float4*)(g_ya + (size_t)s2 * 128 + lane * 4);
            float4 v3 = *(const float4*)(g_ya + (size_t)s3 * 128 + lane * 4);
            a0.x += v0.x; a0.y += v0.y; a0.z += v0.z; a0.w += v0.w;
            a1.x += v1.x; a1.y += v1.y; a1.z += v1.z; a1.w += v1.w;
            a2.x += v2.x; a2.y += v2.y; a2.z += v2.z; a2.w += v2.w;
            a3.x += v3.x; a3.y += v3.y; a3.z += v3.z; a3.w += v3.w;
        }
        for (; i < deg; ++i) {
            int s0 = g_csrc[start + i];
            float4 v0 = *(const float4*)(g_ya + (size_t)s0 * 128 + lane * 4);
            a0.x += v0.x; a0.y += v0.y; a0.z += v0.z; a0.w += v0.w;
        }
        a0.x += a1.x + a2.x + a3.x; a0.y += a1.y + a2.y + a3.y;
        a0.z += a1.z + a2.z + a3.z; a0.w += a1.w + a2.w + a3.w;
        float4 yb = *(const float4*)(g_yb + (size_t)node * 128 + lane * 4);
        float4 r;
        r.x = a0.x * inv + yb.x + bias[lane * 4 + 0];
        r.y = a0.y * inv + yb.y + bias[lane * 4 + 1];
        r.z = a0.z * inv + yb.z + bias[lane * 4 + 2];
        r.w = a0.w * inv + yb.w + bias[lane * 4 + 3];
        if (RELU) {
            r.x = fmaxf(r.x, 0.f); r.y = fmaxf(r.y, 0.f);
            r.z = fmaxf(r.z, 0.f); r.w = fmaxf(r.w, 0.f);
        }
        *(float4*)(out + (size_t)node * 128 + lane * 4) = r;
    } else {
        float2 a0 = make_float2(0.f, 0.f), a1 = a0, a2 = a0, a3 = a0;
        int i = 0;
        for (; i + 3 < deg; i += 4) {
            int s0 = g_csrc[start + i],     s1 = g_csrc[start + i + 1];
            int s2 = g_csrc[start + i + 2], s3 = g_csrc[start + i + 3];
            float2 v0 = *(const float2*)(g_ya + (size_t)s0 * 64 + lane * 2);
            float2 v1 = *(const float2*)(g_ya + (size_t)s1 * 64 + lane * 2);
            float2 v2 = *(const float2*)(g_ya + (size_t)s2 * 64 + lane * 2);
            float2 v3 = *(const float2*)(g_ya + (size_t)s3 * 64 + lane * 2);
            a0.x += v0.x; a0.y += v0.y;  a1.x += v1.x; a1.y += v1.y;
            a2.x += v2.x; a2.y += v2.y;  a3.x += v3.x; a3.y += v3.y;
        }
        for (; i < deg; ++i) {
            int s0 = g_csrc[start + i];
            float2 v0 = *(const float2*)(g_ya + (size_t)s0 * 64 + lane * 2);
            a0.x += v0.x; a0.y += v0.y;
        }
        a0.x += a1.x + a2.x + a3.x; a0.y += a1.y + a2.y + a3.y;
        float2 yb = *(const float2*)(g_yb + (size_t)node * 64 + lane * 2);
        float2 r;
        r.x = a0.x * inv + yb.x + bias[lane * 2 + 0];
        r.y = a0.y * inv + yb.y + bias[lane * 2 + 1];
        if (RELU) { r.x = fmaxf(r.x, 0.f); r.y = fmaxf(r.y, 0.f); }
        *(float2*)(out + (size_t)node * 64 + lane * 2) = r;
    }
}

// ---------------------------------------------------------------------------
extern "C" void kernel_launch(void* const* d_in, const int* in_sizes, int n_in,
                              void* d_out, int out_size) {
    const float* x  = (const float*)d_in[0];
    const void*  ei = d_in[1];
    const float* Wl0 = (const float*)d_in[4];
    const float* bl0 = (const float*)d_in[5];
    const float* Wr0 = (const float*)d_in[6];
    const float* Ws0 = (const float*)d_in[7];
    const float* bs0 = (const float*)d_in[8];
    const float* Wl1 = (const float*)d_in[9];
    const float* bl1 = (const float*)d_in[10];
    const float* Wr1 = (const float*)d_in[11];
    const float* Ws1 = (const float*)d_in[12];
    const float* bs1 = (const float*)d_in[13];
    const float* Wl2 = (const float*)d_in[14];
    const float* bl2 = (const float*)d_in[15];
    const float* Wr2 = (const float*)d_in[16];
    const float* Ws2 = (const float*)d_in[17];
    const float* bs2 = (const float*)d_in[18];
    float* out = (float*)d_out;

    const int S256 = 65536 + 2 * 256 * 256;   // 196608 (W=256)
    const int S128 = 65536 + 2 * 128 * 256;   // 131072 (W=128)
    cudaFuncSetAttribute(tc_gemm_kernel<256, 128, 0>, cudaFuncAttributeMaxDynamicSharedMemorySize, S256);
    cudaFuncSetAttribute(tc_gemm_kernel<256, 128, 1>, cudaFuncAttributeMaxDynamicSharedMemorySize, S256);
    cudaFuncSetAttribute(tc_gemm_kernel<128, 64, 2>,  cudaFuncAttributeMaxDynamicSharedMemorySize, S128);

    const int eBlocks    = (EE + 255) / 256;
    const int gemmBlocks = (NN + 127) / 128;     // 391
    const int aggBlocks  = (NN * 32) / 256;      // 6250
    const int scanBlocks = (NN + 255) / 256;     // 196

    // Order: tc_gemm L0 stays at launch #3 (0-based) for ncu
    prepb_kernel<<<322, 256>>>(Wl0, Wr0, Ws0, Wl1, Wr1, Ws1, Wl2, Wr2, Ws2,
                               bl0, bs0, bl1, bs1, bl2, bs2);               // 0
    zero_cnt_kernel<<<scanBlocks, 256>>>();                                  // 1
    detect_kernel<<<1, 32>>>((const long long*)ei);                          // 2

    tc_gemm_kernel<256, 128, 0><<<gemmBlocks, 256, S256>>>(x, 0);            // 3 (profiled)

    convert_count_kernel<<<eBlocks, 256>>>(ei);                              // 4
    scanA_kernel<<<scanBlocks, 256>>>();                                     // 5
    scanB_kernel<<<1, 256>>>(scanBlocks);                                    // 6
    scanC_kernel<<<scanBlocks, 256>>>();                                     // 7
    fill_kernel<<<eBlocks, 256>>>();                                         // 8

    agg_kernel<128, 1, 1><<<aggBlocks, 256>>>(nullptr, 0);                   // 9

    tc_gemm_kernel<256, 128, 1><<<gemmBlocks, 256, S256>>>(nullptr, 131072); // 10
    agg_kernel<128, 2, 1><<<aggBlocks, 256>>>(nullptr, DD);                  // 11

    tc_gemm_kernel<128, 64, 2><<<gemmBlocks, 256, S128>>>(nullptr, 262144);  // 12
    agg_kernel<64, 0, 0><<<aggBlocks, 256>>>(out, 2 * DD);                   // 13
}

// round 16
// speedup vs baseline: 1.0644x; 1.0499x over previous
#include <cuda_runtime.h>
#include <cuda_bf16.h>
#include <cuda_fp16.h>
#include <cstdint>

#define NN 50000
#define DD 128
#define EE 800000

// ---------------------------------------------------------------------------
// Scratch (device globals — no allocation allowed)
// ---------------------------------------------------------------------------
__device__ __align__(256) __half g_ya16[NN * DD];  // A @ Wl   (fp16)
__device__ __align__(256) float g_yb[NN * DD];     // A @ (Wr+Ws)
__device__ __align__(256) float g_h0[NN * DD];
__device__ __align__(256) float g_h1[NN * DD];
__device__ __align__(256) float g_inv[NN];
__device__ __align__(256) int   g_cnt[NN];
__device__ __align__(256) int   g_rowptr[NN];
__device__ __align__(256) int   g_fill[NN];
__device__ __align__(256) int   g_src[EE];
__device__ __align__(256) int   g_dst[EE];
__device__ __align__(256) int   g_csrc[EE];
__device__ __align__(256) int   g_bsum2[256];      // block sums for scan
__device__ __align__(256) int   g_boff[256];       // block offsets for scan
// Fragment-ready bf16 hi/lo weight images per layer:
// L0 @0: hi 64KB + lo 64KB; L1 @131072: same; L2 @262144: hi 32KB + lo 32KB
__device__ __align__(1024) unsigned char g_wbf[327680];
__device__ __align__(256) float g_bsum[DD + DD + 64];
__device__ int g_is32;

// ---------------------------------------------------------------------------
// Edge dtype probe
// ---------------------------------------------------------------------------
__global__ void detect_kernel(const long long* __restrict__ ei) {
    if (blockIdx.x == 0 && threadIdx.x == 0) {
        int is32 = 0;
        for (int i = 0; i < 64; ++i) {
            long long v = ei[i];
            if (v < 0 || v >= NN) { is32 = 1; break; }
        }
        g_is32 = is32;
    }
}

// Convert edges to int32 arrays + histogram destinations (merged)
__global__ void convert_count_kernel(const void* __restrict__ ei) {
    int e = blockIdx.x * blockDim.x + threadIdx.x;
    if (e >= EE) return;
    int s, d;
    if (g_is32) {
        const int* p = (const int*)ei;
        s = p[e]; d = p[EE + e];
    } else {
        const long long* p = (const long long*)ei;
        s = (int)p[e]; d = (int)p[EE + e];
    }
    g_src[e] = s;
    g_dst[e] = d;
    atomicAdd(&g_cnt[d], 1);
}

// ---------------------------------------------------------------------------
// Weight prep (+ bias fold): FRAGMENT-READY bf16 hi/lo images of [Wl | Wr+Ws].
// B fragment layout for mma m16n8k16 (B is [n][k], n-major, K contiguous):
//   tile (nb = n/8, ks = k/16); lane = (n%8)*4 + ((k%16)%8)/2;
//   word = (k%16)/8; half = k%2;  addr = ((nb*8+ks)*32 + lane)*8 + word*4 + half*2
// nb is GLOBAL across W (concatenated [Wl | Wr+Ws] width).
// ---------------------------------------------------------------------------
__global__ void prepb_kernel(const float* __restrict__ Wl0, const float* __restrict__ Wr0, const float* __restrict__ Ws0,
                             const float* __restrict__ Wl1, const float* __restrict__ Wr1, const float* __restrict__ Ws1,
                             const float* __restrict__ Wl2, const float* __restrict__ Wr2, const float* __restrict__ Ws2,
                             const float* __restrict__ bl0, const float* __restrict__ bs0,
                             const float* __restrict__ bl1, const float* __restrict__ bs1,
                             const float* __restrict__ bl2, const float* __restrict__ bs2) {
    int t = blockIdx.x * blockDim.x + threadIdx.x;
    if (t >= 81920) {
        int b = t - 81920;
        if (b < DD)               g_bsum[b] = bl0[b] + bs0[b];
        else if (b < 2 * DD)      g_bsum[b] = bl1[b - DD] + bs1[b - DD];
        else if (b < 2 * DD + 64) g_bsum[b] = bl2[b - 2 * DD] + bs2[b - 2 * DD];
        return;
    }
    int dout, n, k; size_t base, hsize;
    const float *Wl, *Wr, *Ws;
    if (t < 32768)       { dout = 128; base = 0;      hsize = 65536; int u = t;         n = u >> 7; k = u & 127; Wl = Wl0; Wr = Wr0; Ws = Ws0; }
    else if (t < 65536)  { dout = 128; base = 131072; hsize = 65536; int u = t - 32768; n = u >> 7; k = u & 127; Wl = Wl1; Wr = Wr1; Ws = Ws1; }
    else                 { dout = 64;  base = 262144; hsize = 32768; int u = t - 65536; n = u >> 7; k = u & 127; Wl = Wl2; Wr = Wr2; Ws = Ws2; }
    float val = (n < dout) ? Wl[k * dout + n]
                           : (Wr[k * dout + (n - dout)] + Ws[k * dout + (n - dout)]);
    __nv_bfloat16 hi = __float2bfloat16(val);
    __nv_bfloat16 lo = __float2bfloat16(val - __bfloat162float(hi));
    int nb = n >> 3, ks = k >> 4, kin = k & 15;
    int lane = (n & 7) * 4 + ((kin & 7) >> 1);
    int word = kin >> 3, half = kin & 1;
    size_t off = (size_t)(((nb * 8 + ks) * 32 + lane) * 8 + word * 4 + half * 2);
    *(__nv_bfloat16*)(g_wbf + base + off)         = hi;
    *(__nv_bfloat16*)(g_wbf + base + hsize + off) = lo;
}

// ---------------------------------------------------------------------------
// CSR build: zero, count (merged above), 3-stage scan, fill
// ---------------------------------------------------------------------------
__global__ void zero_cnt_kernel() {
    int t = blockIdx.x * blockDim.x + threadIdx.x;
    if (t < NN) g_cnt[t] = 0;
}
__global__ void scanA_kernel() {
    __shared__ int sh[256];
    int t = threadIdx.x;
    int idx = blockIdx.x * 256 + t;
    sh[t] = (idx < NN) ? g_cnt[idx] : 0;
    __syncthreads();
    for (int off = 128; off > 0; off >>= 1) {
        if (t < off) sh[t] += sh[t + off];
        __syncthreads();
    }
    if (t == 0) g_bsum2[blockIdx.x] = sh[0];
}
__global__ void scanB_kernel(int nblocks) {
    __shared__ int sh[256];
    int t = threadIdx.x;
    sh[t] = (t < nblocks) ? g_bsum2[t] : 0;
    __syncthreads();
    for (int off = 1; off < 256; off <<= 1) {
        int v = (t >= off) ? sh[t - off] : 0;
        __syncthreads();
        sh[t] += v;
        __syncthreads();
    }
    if (t < nblocks) g_boff[t] = (t == 0) ? 0 : sh[t - 1];
}
__global__ void scanC_kernel() {
    __shared__ int sh[256];
    int t = threadIdx.x;
    int idx = blockIdx.x * 256 + t;
    int c = (idx < NN) ? g_cnt[idx] : 0;
    sh[t] = c;
    __syncthreads();
    for (int off = 1; off < 256; off <<= 1) {
        int v = (t >= off) ? sh[t - off] : 0;
        __syncthreads();
        sh[t] += v;
        __syncthreads();
    }
    if (idx < NN) {
        int run = g_boff[blockIdx.x] + sh[t] - c;   // exclusive
        g_rowptr[idx] = run;
        g_fill[idx]   = run;
        g_inv[idx]    = 1.0f / fmaxf((float)c, 1.0f);
    }
}
__global__ void fill_kernel() {
    int e = blockIdx.x * blockDim.x + threadIdx.x;
    if (e >= EE) return;
    int pos = atomicAdd(&g_fill[g_dst[e]], 1);
    g_csrc[pos] = g_src[e];
}

// ---------------------------------------------------------------------------
// mma.sync m16n8k16 bf16 (baseline PTX) + cp.async helpers (sm_80 baseline)
// ---------------------------------------------------------------------------
__device__ __forceinline__ void mma_16816(float* c, const uint32_t* a, const uint32_t* b) {
    asm volatile("mma.sync.aligned.m16n8k16.row.col.f32.bf16.bf16.f32 "
                 "{%0,%1,%2,%3}, {%4,%5,%6,%7}, {%8,%9}, {%0,%1,%2,%3};"
                 : "+f"(c[0]), "+f"(c[1]), "+f"(c[2]), "+f"(c[3])
                 : "r"(a[0]), "r"(a[1]), "r"(a[2]), "r"(a[3]), "r"(b[0]), "r"(b[1]));
}
__device__ __forceinline__ uint32_t smem_u32(const void* p) {
    uint32_t a;
    asm("{ .reg .u64 t; cvta.to.shared.u64 t, %1; cvt.u32.u64 %0, t; }" : "=r"(a) : "l"(p));
    return a;
}
__device__ __forceinline__ void cp_async16(uint32_t saddr, const void* gaddr) {
    asm volatile("cp.async.cg.shared.global [%0], [%1], 16;" :: "r"(saddr), "l"(gaddr));
}

// ---------------------------------------------------------------------------
// Tensor-core GEMM via split-bf16 3-MMA, fat tiles.
// CTA tile: 128 rows x ALL W concatenated output cols. 8 warps 2m x 4n,
// warp tile 64 x (W/4). Warps wn<2 produce g_ya16 (fp16 store);
// wn>=2 produce g_yb (fp32 store).
// SMEM: A_hi 32KB | A_lo 32KB | B_hi W*256 | B_lo W*256
// ---------------------------------------------------------------------------
template<int W, int DOUT, int SRC>
__global__ void __launch_bounds__(256, 1)
tc_gemm_kernel(const float* __restrict__ Ax_ext, int layerOff) {
    constexpr int BIMG = W * 256;            // bytes per B image (hi or lo)
    constexpr int TN = W / 4;                // warp n-extent: 64 (W=256), 32 (W=128)
    constexpr int NT = TN / 8;               // n-subtiles: 8, 4
    constexpr int A_LO = 32768;
    constexpr int B_HI = 65536;
    constexpr int B_LO = 65536 + BIMG;

    extern __shared__ char smem[];
    int tid = threadIdx.x, wid = tid >> 5, lane = tid & 31;
    int wm = wid >> 2, wn = wid & 3;         // 2m x 4n
    int row0 = blockIdx.x * 128;
    const float* A = (SRC == 0) ? Ax_ext : (SRC == 1) ? g_h0 : g_h1;
    uint32_t sbase = smem_u32(smem);

    // --- B full images via cp.async (overlaps with A convert below)
    {
        const char* srcH = (const char*)g_wbf + layerOff;
        const char* srcL = srcH + BIMG;
        constexpr int NCH = BIMG / 16;       // 16B chunks per image
        #pragma unroll
        for (int i = 0; i < NCH / 256; ++i) {
            int c = tid + i * 256;
            cp_async16(sbase + B_HI + c * 16, srcH + c * 16);
            cp_async16(sbase + B_LO + c * 16, srcL + c * 16);
        }
        asm volatile("cp.async.commit_group;");
    }

    // --- load A (128 x 128 f32), split to bf16 hi/lo, store fragment-ready
    #pragma unroll
    for (int i = 0; i < 16; ++i) {
        int f = tid + i * 256;               // 0..4095
        int r = f >> 5;                      // row 0..127
        int k = (f & 31) * 4;
        int grow = row0 + r;
        float4 v = make_float4(0.f, 0.f, 0.f, 0.f);
        if (grow < NN) v = *(const float4*)(A + (size_t)grow * DD + k);
        uint32_t h0, h1, l0, l1;
        {
            __nv_bfloat162 a, b, c, d;
            a.x = __float2bfloat16(v.x); a.y = __float2bfloat16(v.y);
            b.x = __float2bfloat16(v.z); b.y = __float2bfloat16(v.w);
            c.x = __float2bfloat16(v.x - __bfloat162float(a.x));
            c.y = __float2bfloat16(v.y - __bfloat162float(a.y));
            d.x = __float2bfloat16(v.z - __bfloat162float(b.x));
            d.y = __float2bfloat16(v.w - __bfloat162float(b.y));
            h0 = *(uint32_t*)&a; h1 = *(uint32_t*)&b;
            l0 = *(uint32_t*)&c; l1 = *(uint32_t*)&d;
        }
        int rb = r >> 4, g = r & 15;         // rb 0..7
        int ks = k >> 4, kin = k & 15;
        int w = (g >> 3) + ((kin >> 3) << 1);
        int ln0 = (g & 7) * 4 + ((kin & 7) >> 1);
        uint32_t tb = (uint32_t)(((rb * 8 + ks) * 32) * 16 + w * 4);
        *(uint32_t*)(smem + tb + ln0 * 16)              = h0;
        *(uint32_t*)(smem + tb + (ln0 + 1) * 16)        = h1;
        *(uint32_t*)(smem + A_LO + tb + ln0 * 16)       = l0;
        *(uint32_t*)(smem + A_LO + tb + (ln0 + 1) * 16) = l1;
    }

    asm volatile("cp.async.wait_group 0;" ::: "memory");
    __syncthreads();

    float acc[4][NT][4];
    #pragma unroll
    for (int mt = 0; mt < 4; ++mt)
        #pragma unroll
        for (int nt = 0; nt < NT; ++nt)
            #pragma unroll
            for (int j = 0; j < 4; ++j) acc[mt][nt][j] = 0.f;

    #pragma unroll 1
    for (int ks = 0; ks < 8; ++ks) {
        uint4 ah[4], al[4];
        #pragma unroll
        for (int mt = 0; mt < 4; ++mt) {
            int rb = wm * 4 + mt;            // 0..7
            uint32_t ao = (uint32_t)(((rb * 8 + ks) * 32 + lane) * 16);
            ah[mt] = *(const uint4*)(smem + ao);
            al[mt] = *(const uint4*)(smem + A_LO + ao);
        }
        #pragma unroll
        for (int nt = 0; nt < NT; ++nt) {
            int nb = wn * NT + nt;           // global nb over W
            uint32_t bo = (uint32_t)(((nb * 8 + ks) * 32 + lane) * 8);
            uint2 bh = *(const uint2*)(smem + B_HI + bo);
            uint2 bl = *(const uint2*)(smem + B_LO + bo);
            #pragma unroll
            for (int mt = 0; mt < 4; ++mt) {
                mma_16816(acc[mt][nt], (const uint32_t*)&ah[mt], (const uint32_t*)&bh);
                mma_16816(acc[mt][nt], (const uint32_t*)&ah[mt], (const uint32_t*)&bl);
                mma_16816(acc[mt][nt], (const uint32_t*)&al[mt], (const uint32_t*)&bh);
            }
        }
    }

    // --- store: warp n-strip entirely inside one destination matrix
    {
        int gid = lane >> 2, tig = lane & 3;
        if (wn < 2) {
            // ya half: store fp16
            int colbase = wn * TN;
            #pragma unroll
            for (int mt = 0; mt < 4; ++mt) {
                int r0 = row0 + wm * 64 + mt * 16 + gid;
                #pragma unroll
                for (int nt = 0; nt < NT; ++nt) {
                    int col = colbase + nt * 8 + 2 * tig;
                    if (r0 < NN) {
                        __half2 p = __floats2half2_rn(acc[mt][nt][0], acc[mt][nt][1]);
                        *(__half2*)(g_ya16 + (size_t)r0 * DOUT + col) = p;
                    }
                    if (r0 + 8 < NN) {
                        __half2 p = __floats2half2_rn(acc[mt][nt][2], acc[mt][nt][3]);
                        *(__half2*)(g_ya16 + (size_t)(r0 + 8) * DOUT + col) = p;
                    }
                }
            }
        } else {
            // yb half: store fp32
            int colbase = wn * TN - DOUT;
            #pragma unroll
            for (int mt = 0; mt < 4; ++mt) {
                int r0 = row0 + wm * 64 + mt * 16 + gid;
                #pragma unroll
                for (int nt = 0; nt < NT; ++nt) {
                    int col = colbase + nt * 8 + 2 * tig;
                    if (r0 < NN) {
                        float2 v0 = make_float2(acc[mt][nt][0], acc[mt][nt][1]);
                        *(float2*)(g_yb + (size_t)r0 * DOUT + col) = v0;
                    }
                    if (r0 + 8 < NN) {
                        float2 v1 = make_float2(acc[mt][nt][2], acc[mt][nt][3]);
                        *(float2*)(g_yb + (size_t)(r0 + 8) * DOUT + col) = v1;
                    }
                }
            }
        }
    }
}

// ---------------------------------------------------------------------------
// Aggregation: one warp per node, x4 edge unroll, fp16 gathers of ya.
//   h[n] = relu( mean_{e: dst=n}(ya[src_e]) + yb[n] + bias )
// ---------------------------------------------------------------------------
template<int DO, int DST, int RELU>
__global__ void agg_kernel(float* __restrict__ out_ext, int boff) {
    int gt = blockIdx.x * blockDim.x + threadIdx.x;
    int node = gt >> 5;
    int lane = gt & 31;
    if (node >= NN) return;
    float* out = (DST == 0) ? out_ext : (DST == 1) ? g_h0 : g_h1;
    const float* bias = g_bsum + boff;

    int start = g_rowptr[node];
    int deg   = g_cnt[node];
    float inv = g_inv[node];

    if (DO == 128) {
        // each lane covers 4 halves (8 bytes); 32 lanes = 256B row
        float4 a0 = make_float4(0.f, 0.f, 0.f, 0.f), a1 = a0, a2 = a0, a3 = a0;
        int i = 0;
        for (; i + 3 < deg; i += 4) {
            int s0 = g_csrc[start + i],     s1 = g_csrc[start + i + 1];
            int s2 = g_csrc[start + i + 2], s3 = g_csrc[start + i + 3];
            uint2 r0v = ((const uint2*)(g_ya16 + (size_t)s0 * 128))[lane];
            uint2 r1v = ((const uint2*)(g_ya16 + (size_t)s1 * 128))[lane];
            uint2 r2v = ((const uint2*)(g_ya16 + (size_t)s2 * 128))[lane];
            uint2 r3v = ((const uint2*)(g_ya16 + (size_t)s3 * 128))[lane];
            float2 f;
            f = __half22float2(*(__half2*)&r0v.x); a0.x += f.x; a0.y += f.y;
            f = __half22float2(*(__half2*)&r0v.y); a0.z += f.x; a0.w += f.y;
            f = __half22float2(*(__half2*)&r1v.x); a1.x += f.x; a1.y += f.y;
            f = __half22float2(*(__half2*)&r1v.y); a1.z += f.x; a1.w += f.y;
            f = __half22float2(*(__half2*)&r2v.x); a2.x += f.x; a2.y += f.y;
            f = __half22float2(*(__half2*)&r2v.y); a2.z += f.x; a2.w += f.y;
            f = __half22float2(*(__half2*)&r3v.x); a3.x += f.x; a3.y += f.y;
            f = __half22float2(*(__half2*)&r3v.y); a3.z += f.x; a3.w += f.y;
        }
        for (; i < deg; ++i) {
            int s0 = g_csrc[start + i];
            uint2 r0v = ((const uint2*)(g_ya16 + (size_t)s0 * 128))[lane];
            float2 f;
            f = __half22float2(*(__half2*)&r0v.x); a0.x += f.x; a0.y += f.y;
            f = __half22float2(*(__half2*)&r0v.y); a0.z += f.x; a0.w += f.y;
        }
        a0.x += a1.x + a2.x + a3.x; a0.y += a1.y + a2.y + a3.y;
        a0.z += a1.z + a2.z + a3.z; a0.w += a1.w + a2.w + a3.w;
        float4 yb = *(const float4*)(g_yb + (size_t)node * 128 + lane * 4);
        float4 r;
        r.x = a0.x * inv + yb.x + bias[lane * 4 + 0];
        r.y = a0.y * inv + yb.y + bias[lane * 4 + 1];
        r.z = a0.z * inv + yb.z + bias[lane * 4 + 2];
        r.w = a0.w * inv + yb.w + bias[lane * 4 + 3];
        if (RELU) {
            r.x = fmaxf(r.x, 0.f); r.y = fmaxf(r.y, 0.f);
            r.z = fmaxf(r.z, 0.f); r.w = fmaxf(r.w, 0.f);
        }
        *(float4*)(out + (size_t)node * 128 + lane * 4) = r;
    } else {
        // each lane covers 2 halves (4 bytes); 32 lanes = 128B row
        float2 a0 = make_float2(0.f, 0.f), a1 = a0, a2 = a0, a3 = a0;
        int i = 0;
        for (; i + 3 < deg; i += 4) {
            int s0 = g_csrc[start + i],     s1 = g_csrc[start + i + 1];
            int s2 = g_csrc[start + i + 2], s3 = g_csrc[start + i + 3];
            uint32_t r0v = ((const uint32_t*)(g_ya16 + (size_t)s0 * 64))[lane];
            uint32_t r1v = ((const uint32_t*)(g_ya16 + (size_t)s1 * 64))[lane];
            uint32_t r2v = ((const uint32_t*)(g_ya16 + (size_t)s2 * 64))[lane];
            uint32_t r3v = ((const uint32_t*)(g_ya16 + (size_t)s3 * 64))[lane];
            float2 f;
            f = __half22float2(*(__half2*)&r0v); a0.x += f.x; a0.y += f.y;
            f = __half22float2(*(__half2*)&r1v); a1.x += f.x; a1.y += f.y;
            f = __half22float2(*(__half2*)&r2v); a2.x += f.x; a2.y += f.y;
            f = __half22float2(*(__half2*)&r3v); a3.x += f.x; a3.y += f.y;
        }
        for (; i < deg; ++i) {
            int s0 = g_csrc[start + i];
            uint32_t r0v = ((const uint32_t*)(g_ya16 + (size_t)s0 * 64))[lane];
            float2 f = __half22float2(*(__half2*)&r0v);
            a0.x += f.x; a0.y += f.y;
        }
        a0.x += a1.x + a2.x + a3.x; a0.y += a1.y + a2.y + a3.y;
        float2 yb = *(const float2*)(g_yb + (size_t)node * 64 + lane * 2);
        float2 r;
        r.x = a0.x * inv + yb.x + bias[lane * 2 + 0];
        r.y = a0.y * inv + yb.y + bias[lane * 2 + 1];
        if (RELU) { r.x = fmaxf(r.x, 0.f); r.y = fmaxf(r.y, 0.f); }
        *(float2*)(out + (size_t)node * 64 + lane * 2) = r;
    }
}

// ---------------------------------------------------------------------------
extern "C" void kernel_launch(void* const* d_in, const int* in_sizes, int n_in,
                              void* d_out, int out_size) {
    const float* x  = (const float*)d_in[0];
    const void*  ei = d_in[1];
    const float* Wl0 = (const float*)d_in[4];
    const float* bl0 = (const float*)d_in[5];
    const float* Wr0 = (const float*)d_in[6];
    const float* Ws0 = (const float*)d_in[7];
    const float* bs0 = (const float*)d_in[8];
    const float* Wl1 = (const float*)d_in[9];
    const float* bl1 = (const float*)d_in[10];
    const float* Wr1 = (const float*)d_in[11];
    const float* Ws1 = (const float*)d_in[12];
    const float* bs1 = (const float*)d_in[13];
    const float* Wl2 = (const float*)d_in[14];
    const float* bl2 = (const float*)d_in[15];
    const float* Wr2 = (const float*)d_in[16];
    const float* Ws2 = (const float*)d_in[17];
    const float* bs2 = (const float*)d_in[18];
    float* out = (float*)d_out;

    const int S256 = 65536 + 2 * 256 * 256;   // 196608 (W=256)
    const int S128 = 65536 + 2 * 128 * 256;   // 131072 (W=128)
    cudaFuncSetAttribute(tc_gemm_kernel<256, 128, 0>, cudaFuncAttributeMaxDynamicSharedMemorySize, S256);
    cudaFuncSetAttribute(tc_gemm_kernel<256, 128, 1>, cudaFuncAttributeMaxDynamicSharedMemorySize, S256);
    cudaFuncSetAttribute(tc_gemm_kernel<128, 64, 2>,  cudaFuncAttributeMaxDynamicSharedMemorySize, S128);

    const int eBlocks    = (EE + 255) / 256;
    const int gemmBlocks = (NN + 127) / 128;     // 391
    const int aggBlocks  = (NN * 32) / 256;      // 6250
    const int scanBlocks = (NN + 255) / 256;     // 196

    // Order: tc_gemm L0 stays at launch #3 (0-based) for ncu
    prepb_kernel<<<322, 256>>>(Wl0, Wr0, Ws0, Wl1, Wr1, Ws1, Wl2, Wr2, Ws2,
                               bl0, bs0, bl1, bs1, bl2, bs2);               // 0
    zero_cnt_kernel<<<scanBlocks, 256>>>();                                  // 1
    detect_kernel<<<1, 32>>>((const long long*)ei);                          // 2

    tc_gemm_kernel<256, 128, 0><<<gemmBlocks, 256, S256>>>(x, 0);            // 3 (profiled)

    convert_count_kernel<<<eBlocks, 256>>>(ei);                              // 4
    scanA_kernel<<<scanBlocks, 256>>>();                                     // 5
    scanB_kernel<<<1, 256>>>(scanBlocks);                                    // 6
    scanC_kernel<<<scanBlocks, 256>>>();                                     // 7
    fill_kernel<<<eBlocks, 256>>>();                                         // 8

    agg_kernel<128, 1, 1><<<aggBlocks, 256>>>(nullptr, 0);                   // 9

    tc_gemm_kernel<256, 128, 1><<<gemmBlocks, 256, S256>>>(nullptr, 131072); // 10
    agg_kernel<128, 2, 1><<<aggBlocks, 256>>>(nullptr, DD);                  // 11

    tc_gemm_kernel<128, 64, 2><<<gemmBlocks, 256, S128>>>(nullptr, 262144);  // 12
    agg_kernel<64, 0, 0><<<aggBlocks, 256>>>(out, 2 * DD);                   // 13
}